// round 13
// baseline (speedup 1.0000x reference)
#include <cuda_runtime.h>
#include <cuda_bf16.h>
#include <cstdint>

// Inverse of f(x) = a*x + (1-a)*softplus(x), a = 0.1 + 0.4*sigmoid(raw_alpha).
//
// R12: R9 math (ONE Halley iteration from shifted init) fed by a double-
// buffered cp.async.bulk (TMA/UBLKCP) pipeline: bulk copies GMEM->SMEM are
// issued by one thread and tracked by mbarrier transaction counts, so
// in-flight bytes are decoupled from register pressure (the R10/R11 failure
// mode). 8KB chunks, 2 buffers/CTA, persistent grid 7 CTAs/SM.

#define LN2F   0.6931471805599453f
#define L2EF   1.4426950408889634f
#define CHUNK_F4    512                  // float4s per chunk = 8KB
#define CHUNK_BYTES (CHUNK_F4 * 16)

typedef unsigned long long ull;

__device__ __forceinline__ ull pack2(float lo, float hi) {
    ull r; asm("mov.b64 %0, {%1, %2};" : "=l"(r) : "f"(lo), "f"(hi)); return r;
}
__device__ __forceinline__ void unpack2(ull v, float& lo, float& hi) {
    asm("mov.b64 {%0, %1}, %2;" : "=f"(lo), "=f"(hi) : "l"(v));
}
__device__ __forceinline__ ull fma2(ull a, ull b, ull c) {
    ull d; asm("fma.rn.f32x2 %0, %1, %2, %3;" : "=l"(d) : "l"(a), "l"(b), "l"(c)); return d;
}
__device__ __forceinline__ ull mul2(ull a, ull b) {
    ull d; asm("mul.rn.f32x2 %0, %1, %2;" : "=l"(d) : "l"(a), "l"(b)); return d;
}
__device__ __forceinline__ ull add2(ull a, ull b) {
    ull d; asm("add.rn.f32x2 %0, %1, %2;" : "=l"(d) : "l"(a), "l"(b)); return d;
}
__device__ __forceinline__ float rcp_approx(float x) {
    float r; asm("rcp.approx.ftz.f32 %0, %1;" : "=f"(r) : "f"(x)); return r;
}
__device__ __forceinline__ float ex2_approx(float x) {
    float r; asm("ex2.approx.ftz.f32 %0, %1;" : "=f"(r) : "f"(x)); return r;
}
__device__ __forceinline__ float lg2_approx(float x) {
    float r; asm("lg2.approx.ftz.f32 %0, %1;" : "=f"(r) : "f"(x)); return r;
}

struct Consts {
    ull k2, negc2, one2, ln2_2;
    ull a2, na2, oma2, noma2, omah2;
    float a, oma, omah, inv_a, c;
};

// One full Halley iteration on a packed lane pair (R6/R9 body).
__device__ __forceinline__ ull halley_iter(ull X, ull Y, const Consts& C) {
    float x0, x1; unpack2(X, x0, x1);
    float e0 = ex2_approx(-fabsf(x0) * L2EF);        // MUFU EX2
    float e1 = ex2_approx(-fabsf(x1) * L2EF);
    ull  E  = pack2(e0, e1);
    ull  D  = add2(E, C.one2);                       // d = 1+e
    float d0, d1; unpack2(D, d0, d1);
    float l0 = lg2_approx(d0);                       // MUFU LG2
    float l1 = lg2_approx(d1);
    ull  SP = fma2(pack2(l0, l1), C.ln2_2,
                   pack2(fmaxf(x0, 0.0f), fmaxf(x1, 0.0f)));
    ull  G  = fma2(C.noma2, SP, fma2(C.na2, X, Y));  // y - f(x)
    ull  S  = pack2((x0 > 0.0f) ? 1.0f : e0,
                    (x1 > 0.0f) ? 1.0f : e1);
    ull  P  = fma2(C.a2, D, mul2(C.oma2, S));        // d * f'(x)
    ull  DEN = fma2(P, P, mul2(G, mul2(C.omah2, E)));
    float dn0, dn1; unpack2(DEN, dn0, dn1);
    ull  R  = pack2(rcp_approx(dn0), rcp_approx(dn1)); // MUFU RCP x2
    ull  GPD = mul2(G, mul2(P, D));
    return fma2(GPD, R, X);
}

__device__ __forceinline__ float4 solve4(float4 y4, const Consts& C) {
    ull Y01 = pack2(y4.x, y4.y);
    ull Y23 = pack2(y4.z, y4.w);
    ull M01 = pack2(fminf(y4.x, 0.0f), fminf(y4.y, 0.0f));
    ull M23 = pack2(fminf(y4.z, 0.0f), fminf(y4.w, 0.0f));
    ull XA = fma2(M01, C.k2, add2(Y01, C.negc2));
    ull XB = fma2(M23, C.k2, add2(Y23, C.negc2));
    XA = halley_iter(XA, Y01, C);
    XB = halley_iter(XB, Y23, C);
    float4 x4;
    unpack2(XA, x4.x, x4.y);
    unpack2(XB, x4.z, x4.w);
    return x4;
}

__device__ __forceinline__ float halley_scalar(float y, const Consts& C) {
    float x = ((y > 0.0f) ? y : y * C.inv_a) - C.c;
    float e  = ex2_approx(-fabsf(x) * L2EF);
    float d  = 1.0f + e;
    float sp = fmaf(LN2F, lg2_approx(d), fmaxf(x, 0.0f));
    float g  = fmaf(-C.oma, sp, fmaf(-C.a, x, y));
    float s  = (x > 0.0f) ? 1.0f : e;
    float P  = fmaf(C.a, d, C.oma * s);
    float den = fmaf(P, P, g * (C.omah * e));
    return fmaf(g * (P * d), rcp_approx(den), x);
}

// ---- mbarrier / bulk-copy primitives ----
__device__ __forceinline__ void mbar_init(uint32_t mbar, uint32_t count) {
    asm volatile("mbarrier.init.shared.b64 [%0], %1;" :: "r"(mbar), "r"(count) : "memory");
}
__device__ __forceinline__ void mbar_expect_tx(uint32_t mbar, uint32_t bytes) {
    asm volatile("mbarrier.arrive.expect_tx.shared.b64 _, [%0], %1;"
                 :: "r"(mbar), "r"(bytes) : "memory");
}
__device__ __forceinline__ void bulk_g2s(uint32_t dst_smem, const void* src_gmem,
                                         uint32_t bytes, uint32_t mbar) {
    asm volatile("cp.async.bulk.shared::cta.global.mbarrier::complete_tx::bytes "
                 "[%0], [%1], %2, [%3];"
                 :: "r"(dst_smem), "l"(src_gmem), "r"(bytes), "r"(mbar) : "memory");
}
__device__ __forceinline__ void mbar_wait(uint32_t mbar, uint32_t parity) {
    asm volatile(
        "{\n\t"
        ".reg .pred P;\n"
        "WAIT_%=:\n\t"
        "mbarrier.try_wait.parity.acquire.cta.shared::cta.b64 P, [%0], %1, 0x989680;\n\t"
        "@P bra DONE_%=;\n\t"
        "bra WAIT_%=;\n"
        "DONE_%=:\n\t"
        "}"
        :: "r"(mbar), "r"(parity) : "memory");
}

__global__ __launch_bounds__(256, 7)
void inv_leaky_softplus_kernel(const float4* __restrict__ in,
                               const float* __restrict__ raw_alpha,
                               float4* __restrict__ out,
                               int n4, int n_rem,
                               const float* __restrict__ rem_in,
                               float* __restrict__ rem_out) {
    __shared__ alignas(128) float4 buf[2][CHUNK_F4];   // 2 x 8KB
    __shared__ alignas(8) unsigned long long mbar[2];

    int tid = threadIdx.x;

    if (tid == 0) {
        uint32_t m0 = (uint32_t)__cvta_generic_to_shared(&mbar[0]);
        uint32_t m1 = (uint32_t)__cvta_generic_to_shared(&mbar[1]);
        mbar_init(m0, 1);
        mbar_init(m1, 1);
    }
    asm volatile("fence.proxy.async.shared::cta;" ::: "memory");
    __syncthreads();

    float ra  = raw_alpha[0];
    float a   = fmaf(0.4f, rcp_approx(1.0f + ex2_approx(-ra * L2EF)), 0.1f);
    float oma = 1.0f - a;
    float iva = rcp_approx(a);
    iva = iva * (2.0f - a * iva);

    Consts C;
    C.a = a; C.oma = oma; C.omah = 0.5f * oma; C.inv_a = iva; C.c = oma * LN2F;
    C.k2    = pack2(iva - 1.0f, iva - 1.0f);
    C.negc2 = pack2(-C.c, -C.c);
    C.one2  = pack2(1.0f, 1.0f);
    C.ln2_2 = pack2(LN2F, LN2F);
    C.a2    = pack2(a, a);
    C.na2   = pack2(-a, -a);
    C.oma2  = pack2(oma, oma);
    C.noma2 = pack2(-oma, -oma);
    C.omah2 = pack2(C.omah, C.omah);

    int gtid    = blockIdx.x * blockDim.x + tid;
    int gstride = gridDim.x * blockDim.x;
    int nchunks = n4 / CHUNK_F4;

    // scalar tail (n % 4)
    if (gtid < n_rem) rem_out[gtid] = halley_scalar(rem_in[gtid], C);

    // leftover float4s beyond the last full chunk (register LDG path)
    for (int r = nchunks * CHUNK_F4 + gtid; r < n4; r += gstride)
        out[r] = solve4(in[r], C);

    uint32_t mb[2];
    mb[0] = (uint32_t)__cvta_generic_to_shared(&mbar[0]);
    mb[1] = (uint32_t)__cvta_generic_to_shared(&mbar[1]);
    uint32_t sb[2];
    sb[0] = (uint32_t)__cvta_generic_to_shared(&buf[0][0]);
    sb[1] = (uint32_t)__cvta_generic_to_shared(&buf[1][0]);

    int phase[2] = {0, 0};
    int c = blockIdx.x;

    // prime the pipeline: issue chunk c into buffer 0
    if (c < nchunks && tid == 0) {
        mbar_expect_tx(mb[0], CHUNK_BYTES);
        bulk_g2s(sb[0], in + (size_t)c * CHUNK_F4, CHUNK_BYTES, mb[0]);
    }

    int it = 0;
    while (c < nchunks) {
        int s  = it & 1;
        int cn = c + gridDim.x;
        // issue next chunk into the other buffer before waiting on this one
        if (cn < nchunks && tid == 0) {
            mbar_expect_tx(mb[s ^ 1], CHUNK_BYTES);
            bulk_g2s(sb[s ^ 1], in + (size_t)cn * CHUNK_F4, CHUNK_BYTES, mb[s ^ 1]);
        }
        mbar_wait(mb[s], phase[s]);
        phase[s] ^= 1;

        // consume: 2 float4 per thread (2 independent pair-chains each)
        float4 y0 = buf[s][tid];
        float4 y1 = buf[s][tid + 256];
        size_t base = (size_t)c * CHUNK_F4;
        out[base + tid]       = solve4(y0, C);
        out[base + tid + 256] = solve4(y1, C);

        __syncthreads();   // buffer s free before it is re-filled at it+1's issue
        c = cn;
        ++it;
    }
}

extern "C" void kernel_launch(void* const* d_in, const int* in_sizes, int n_in,
                              void* d_out, int out_size) {
    const float* inp   = (const float*)d_in[0];
    const float* alpha = (const float*)d_in[1];
    float*       outp  = (float*)d_out;

    int n     = in_sizes[0];
    int n4    = n >> 2;
    int n_rem = n & 3;
    const float* rem_in  = inp  + (size_t)n4 * 4;
    float*       rem_out = outp + (size_t)n4 * 4;

    int threads = 256;
    int blocks  = 148 * 7;               // persistent: 7 CTAs per SM

    inv_leaky_softplus_kernel<<<blocks, threads>>>(
        (const float4*)inp, alpha, (float4*)outp, n4, n_rem, rem_in, rem_out);
}

// round 14
// speedup vs baseline: 1.2116x; 1.2116x over previous
#include <cuda_runtime.h>
#include <cuda_bf16.h>

// Inverse of f(x) = a*x + (1-a)*softplus(x), a = 0.1 + 0.4*sigmoid(raw_alpha).
//
// R13 (final form): R9 champion verbatim — ONE Halley iteration from the
// shifted init (norm rel err ~1e-4, 10x under the 1e-3 bar), f32x2-packed
// FMA work, 8 elem/thread as 2 half-strided float4s with front-batched
// loads — plus evict-first (.cs) hints on the STORE stream only.
// R9 already achieves 7.2 TB/s = 90% of HBM spec (33.5M x 8B / 37.3us);
// every restructuring attempt (R10 4-way MLP, R11 persistent, R12 TMA
// pipeline) regressed. This is the memory roofline.

#define LN2F   0.6931471805599453f
#define L2EF   1.4426950408889634f

typedef unsigned long long ull;

__device__ __forceinline__ ull pack2(float lo, float hi) {
    ull r; asm("mov.b64 %0, {%1, %2};" : "=l"(r) : "f"(lo), "f"(hi)); return r;
}
__device__ __forceinline__ void unpack2(ull v, float& lo, float& hi) {
    asm("mov.b64 {%0, %1}, %2;" : "=f"(lo), "=f"(hi) : "l"(v));
}
__device__ __forceinline__ ull fma2(ull a, ull b, ull c) {
    ull d; asm("fma.rn.f32x2 %0, %1, %2, %3;" : "=l"(d) : "l"(a), "l"(b), "l"(c)); return d;
}
__device__ __forceinline__ ull mul2(ull a, ull b) {
    ull d; asm("mul.rn.f32x2 %0, %1, %2;" : "=l"(d) : "l"(a), "l"(b)); return d;
}
__device__ __forceinline__ ull add2(ull a, ull b) {
    ull d; asm("add.rn.f32x2 %0, %1, %2;" : "=l"(d) : "l"(a), "l"(b)); return d;
}
__device__ __forceinline__ float rcp_approx(float x) {
    float r; asm("rcp.approx.ftz.f32 %0, %1;" : "=f"(r) : "f"(x)); return r;
}
__device__ __forceinline__ float ex2_approx(float x) {
    float r; asm("ex2.approx.ftz.f32 %0, %1;" : "=f"(r) : "f"(x)); return r;
}
__device__ __forceinline__ float lg2_approx(float x) {
    float r; asm("lg2.approx.ftz.f32 %0, %1;" : "=f"(r) : "f"(x)); return r;
}

__device__ __forceinline__ void stcs4(float4* p, float4 v) {
    asm("st.global.cs.v4.f32 [%0], {%1,%2,%3,%4};"
        :: "l"(p), "f"(v.x), "f"(v.y), "f"(v.z), "f"(v.w) : "memory");
}

struct Consts {
    ull k2;      // splat(inv_a - 1)
    ull negc2;   // splat(-(1-a)*ln2)
    ull one2;    // splat(1.0)
    ull ln2_2;   // splat(ln2)
    ull a2, na2, oma2, noma2, omah2;
    float a, oma, omah, inv_a, c;   // scalar copies for the tail path
};

// One full Halley iteration on a packed lane pair (R6 body — best schedule).
__device__ __forceinline__ ull halley_iter(ull X, ull Y, const Consts& C) {
    float x0, x1; unpack2(X, x0, x1);
    float e0 = ex2_approx(-fabsf(x0) * L2EF);        // MUFU EX2
    float e1 = ex2_approx(-fabsf(x1) * L2EF);
    ull  E  = pack2(e0, e1);
    ull  D  = add2(E, C.one2);                       // d = 1+e
    float d0, d1; unpack2(D, d0, d1);
    float l0 = lg2_approx(d0);                       // MUFU LG2
    float l1 = lg2_approx(d1);
    ull  SP = fma2(pack2(l0, l1), C.ln2_2,
                   pack2(fmaxf(x0, 0.0f), fmaxf(x1, 0.0f)));  // softplus
    ull  G  = fma2(C.noma2, SP, fma2(C.na2, X, Y));  // y - f(x)
    ull  S  = pack2((x0 > 0.0f) ? 1.0f : e0,
                    (x1 > 0.0f) ? 1.0f : e1);
    ull  P  = fma2(C.a2, D, mul2(C.oma2, S));        // d * f'(x)
    ull  DEN = fma2(P, P, mul2(G, mul2(C.omah2, E)));// P^2 - ft*(1-a)e/2 > 0
    float dn0, dn1; unpack2(DEN, dn0, dn1);
    ull  R  = pack2(rcp_approx(dn0), rcp_approx(dn1)); // MUFU RCP x2
    ull  GPD = mul2(G, mul2(P, D));                  // -ft*P*d
    return fma2(GPD, R, X);
}

// Solve 4 elements (one float4): two independent packed pair-chains.
__device__ __forceinline__ float4 solve4(float4 y4, const Consts& C) {
    ull Y01 = pack2(y4.x, y4.y);
    ull Y23 = pack2(y4.z, y4.w);
    // init: x0 = y + min(y,0)*(1/a - 1) - (1-a)*ln2
    ull M01 = pack2(fminf(y4.x, 0.0f), fminf(y4.y, 0.0f));
    ull M23 = pack2(fminf(y4.z, 0.0f), fminf(y4.w, 0.0f));
    ull XA = fma2(M01, C.k2, add2(Y01, C.negc2));
    ull XB = fma2(M23, C.k2, add2(Y23, C.negc2));
    XA = halley_iter(XA, Y01, C);                    // single Halley step
    XB = halley_iter(XB, Y23, C);
    float4 x4;
    unpack2(XA, x4.x, x4.y);
    unpack2(XB, x4.z, x4.w);
    return x4;
}

// Scalar path for tail elements (same math: 1 Halley step).
__device__ __forceinline__ float halley_scalar(float y, const Consts& C) {
    float x = ((y > 0.0f) ? y : y * C.inv_a) - C.c;
    float e  = ex2_approx(-fabsf(x) * L2EF);
    float d  = 1.0f + e;
    float sp = fmaf(LN2F, lg2_approx(d), fmaxf(x, 0.0f));
    float g  = fmaf(-C.oma, sp, fmaf(-C.a, x, y));
    float s  = (x > 0.0f) ? 1.0f : e;
    float P  = fmaf(C.a, d, C.oma * s);
    float den = fmaf(P, P, g * (C.omah * e));
    return fmaf(g * (P * d), rcp_approx(den), x);
}

__global__ __launch_bounds__(256)
void inv_leaky_softplus_kernel(const float4* __restrict__ in,
                               const float* __restrict__ raw_alpha,
                               float4* __restrict__ out,
                               int n4, int half_stride, int n_rem,
                               const float* __restrict__ rem_in,
                               float* __restrict__ rem_out) {
    float ra  = raw_alpha[0];
    float a   = fmaf(0.4f, rcp_approx(1.0f + ex2_approx(-ra * L2EF)), 0.1f);
    float oma = 1.0f - a;
    float iva = rcp_approx(a);
    iva = iva * (2.0f - a * iva);    // refine reciprocal to full precision

    Consts C;
    C.a = a; C.oma = oma; C.omah = 0.5f * oma; C.inv_a = iva; C.c = oma * LN2F;
    C.k2    = pack2(iva - 1.0f, iva - 1.0f);
    C.negc2 = pack2(-C.c, -C.c);
    C.one2  = pack2(1.0f, 1.0f);
    C.ln2_2 = pack2(LN2F, LN2F);
    C.a2    = pack2(a, a);
    C.na2   = pack2(-a, -a);
    C.oma2  = pack2(oma, oma);
    C.noma2 = pack2(-oma, -oma);
    C.omah2 = pack2(C.omah, C.omah);

    int i = blockIdx.x * blockDim.x + threadIdx.x;   // first float4
    int j = i + half_stride;                          // second float4

    bool doA = (i < n4);
    bool doB = (j < n4) && (i < half_stride);

    float4 ya, yb;
    if (doA) ya = in[i];           // both loads issued before compute (MLP)
    if (doB) yb = in[j];

    if (doA) {
        float4 xa = solve4(ya, C);
        stcs4(out + i, xa);        // evict-first store (touch-once stream)
    }
    if (doB) {
        float4 xb = solve4(yb, C);
        stcs4(out + j, xb);
    }

    if (i < n_rem) {
        rem_out[i] = halley_scalar(rem_in[i], C);
    }
}

extern "C" void kernel_launch(void* const* d_in, const int* in_sizes, int n_in,
                              void* d_out, int out_size) {
    const float* inp   = (const float*)d_in[0];
    const float* alpha = (const float*)d_in[1];
    float*       outp  = (float*)d_out;

    int n     = in_sizes[0];
    int n4    = n >> 2;
    int n_rem = n & 3;
    const float* rem_in  = inp  + (size_t)n4 * 4;
    float*       rem_out = outp + (size_t)n4 * 4;

    int half = (n4 + 1) >> 1;            // float4s handled by the "A" slot
    int threads = 256;
    int work = (half > n_rem) ? half : n_rem;
    int blocks = (work + threads - 1) / threads;
    if (blocks < 1) blocks = 1;

    inv_leaky_softplus_kernel<<<blocks, threads>>>(
        (const float4*)inp, alpha, (float4*)outp, n4, half, n_rem, rem_in, rem_out);
}